// round 2
// baseline (speedup 1.0000x reference)
#include <cuda_runtime.h>
#include <math.h>

#define B_    64
#define S_    4096
#define E_    266
#define HID_  512
#define NH_   128
#define M_    (B_ * NH_)   /* 8192 rows */

// ---------------- device scratch (no allocations allowed) ----------------
__device__ float g_zw[B_ * HID_];        // z @ w_in
__device__ float g_ew[NH_ * HID_];       // emb @ w_in + b_in
__device__ float g_buf[2][M_ * HID_];    // ping-pong activations (2 x 16 MB)
__device__ float g_sinc[M_];             // coeffs[...,0]
__device__ float g_cosc[M_];             // coeffs[...,1]

__device__ __forceinline__ float silu(float v) {
    return v / (1.0f + __expf(-v));
}

// ---------------- z @ w_in : (64 x 266) @ (266 x 512) ----------------
__global__ void k_zw(const float* __restrict__ z, const float* __restrict__ w_in) {
    __shared__ float zr[E_];
    const int b = blockIdx.y;
    for (int e = threadIdx.x; e < E_; e += blockDim.x) zr[e] = z[b * E_ + e];
    __syncthreads();
    const int d = blockIdx.x * blockDim.x + threadIdx.x;
    float acc = 0.f;
    #pragma unroll 2
    for (int e = 0; e < E_; e++) acc = fmaf(zr[e], __ldg(w_in + e * HID_ + d), acc);
    g_zw[b * HID_ + d] = acc;
}

// ---------------- emb @ w_in + b_in : (128 x 266) @ (266 x 512) ----------------
__global__ void k_ew(const float* __restrict__ emb, const float* __restrict__ w_in,
                     const float* __restrict__ b_in) {
    __shared__ float er[E_];
    const int h = blockIdx.y;
    for (int e = threadIdx.x; e < E_; e += blockDim.x) er[e] = emb[h * E_ + e];
    __syncthreads();
    const int d = blockIdx.x * blockDim.x + threadIdx.x;
    float acc = b_in[d];
    #pragma unroll 2
    for (int e = 0; e < E_; e++) acc = fmaf(er[e], __ldg(w_in + e * HID_ + d), acc);
    g_ew[h * HID_ + d] = acc;
}

// ---------------- h0 = silu(zw[b] + ew[h]) ----------------
__global__ void k_h0() {
    const int row = blockIdx.y;            // 0..8191
    const int d = blockIdx.x * blockDim.x + threadIdx.x;
    const int b = row >> 7;
    const int h = row & (NH_ - 1);
    g_buf[0][row * HID_ + d] = silu(g_zw[b * HID_ + d] + g_ew[h * HID_ + d]);
}

// ---------------- tiled fp32 GEMM: C = silu(A @ W + bias) ----------------
// A: (8192 x 512), W: (512 x 512) row-major, C: (8192 x 512)
// BM=BN=128, BK=8, 256 threads, 8x8 per thread.
template <bool SILU>
__global__ void __launch_bounds__(256) k_gemm(int src, int dst,
                                              const float* __restrict__ W,
                                              const float* __restrict__ bias) {
    __shared__ float As[8][132];   // [k][m], padded
    __shared__ float Bs[8][128];   // [k][n]

    const float* __restrict__ A = g_buf[src];
    float* __restrict__ C = g_buf[dst];

    const int tid  = threadIdx.x;
    const int m0   = blockIdx.y * 128;
    const int n0   = blockIdx.x * 128;
    const int trow = (tid / 16) * 8;
    const int tcol = (tid % 16) * 8;

    const int aRow = tid >> 1;            // 0..127
    const int aCol = (tid & 1) * 4;       // 0 or 4
    const int bRow = tid >> 5;            // 0..7
    const int bCol = (tid & 31) * 4;      // 0..124

    const float* Aptr = A + (size_t)(m0 + aRow) * HID_ + aCol;
    const float* Wptr = W + (size_t)bRow * HID_ + n0 + bCol;

    float acc[8][8] = {};

    float4 av = *(const float4*)(Aptr);
    float4 bv = *(const float4*)(Wptr);

    for (int k0 = 0; k0 < HID_; k0 += 8) {
        __syncthreads();
        As[aCol + 0][aRow] = av.x;
        As[aCol + 1][aRow] = av.y;
        As[aCol + 2][aRow] = av.z;
        As[aCol + 3][aRow] = av.w;
        *(float4*)&Bs[bRow][bCol] = bv;
        __syncthreads();

        if (k0 + 8 < HID_) {
            av = *(const float4*)(Aptr + (k0 + 8));
            bv = *(const float4*)(Wptr + (size_t)(k0 + 8) * HID_);
        }

        #pragma unroll
        for (int k = 0; k < 8; k++) {
            float4 a0 = *(const float4*)&As[k][trow];
            float4 a1 = *(const float4*)&As[k][trow + 4];
            float4 b0 = *(const float4*)&Bs[k][tcol];
            float4 b1 = *(const float4*)&Bs[k][tcol + 4];
            float ar[8] = {a0.x, a0.y, a0.z, a0.w, a1.x, a1.y, a1.z, a1.w};
            float br[8] = {b0.x, b0.y, b0.z, b0.w, b1.x, b1.y, b1.z, b1.w};
            #pragma unroll
            for (int i = 0; i < 8; i++)
                #pragma unroll
                for (int j = 0; j < 8; j++)
                    acc[i][j] = fmaf(ar[i], br[j], acc[i][j]);
        }
    }

    float bvreg[8];
    #pragma unroll
    for (int j = 0; j < 8; j++) bvreg[j] = bias[n0 + tcol + j];

    #pragma unroll
    for (int i = 0; i < 8; i++) {
        const int m = m0 + trow + i;
        float* crow = C + (size_t)m * HID_ + n0 + tcol;
        #pragma unroll
        for (int j = 0; j < 8; j += 4) {
            float4 v;
            v.x = acc[i][j + 0] + bvreg[j + 0];
            v.y = acc[i][j + 1] + bvreg[j + 1];
            v.z = acc[i][j + 2] + bvreg[j + 2];
            v.w = acc[i][j + 3] + bvreg[j + 3];
            if (SILU) {
                v.x = silu(v.x); v.y = silu(v.y); v.z = silu(v.z); v.w = silu(v.w);
            }
            *(float4*)(crow + j) = v;
        }
    }
}

// ---------------- final projection: coeffs = H @ w_out + b_out ----------------
// one block (128 threads) per row
__global__ void k_coeff(int src, const float* __restrict__ w_out,
                        const float* __restrict__ b_out) {
    const int row = blockIdx.x;
    const float* hp = g_buf[src] + (size_t)row * HID_;
    float s = 0.f, c = 0.f;
    for (int k = threadIdx.x; k < HID_; k += 128) {
        const float a = hp[k];
        s = fmaf(a, w_out[2 * k + 0], s);
        c = fmaf(a, w_out[2 * k + 1], c);
    }
    #pragma unroll
    for (int o = 16; o > 0; o >>= 1) {
        s += __shfl_down_sync(0xffffffffu, s, o);
        c += __shfl_down_sync(0xffffffffu, c, o);
    }
    __shared__ float ss[4], cs[4];
    const int w = threadIdx.x >> 5;
    if ((threadIdx.x & 31) == 0) { ss[w] = s; cs[w] = c; }
    __syncthreads();
    if (threadIdx.x == 0) {
        g_sinc[row] = ss[0] + ss[1] + ss[2] + ss[3] + b_out[0];
        g_cosc[row] = cs[0] + cs[1] + cs[2] + cs[3] + b_out[1];
    }
}

// ---------------- synthesis with integer-frequency recurrence ----------------
// FREQS = [1..128]; cos(h*th), sin(h*th) via angle addition from one sincos.
__global__ void k_synth(const float* __restrict__ tx, float* __restrict__ out) {
    __shared__ float sc[NH_], cc[NH_];
    const int b = blockIdx.y;
    if (threadIdx.x < NH_) {
        sc[threadIdx.x] = g_sinc[b * NH_ + threadIdx.x];
        cc[threadIdx.x] = g_cosc[b * NH_ + threadIdx.x];
    }
    __syncthreads();
    const int sI = blockIdx.x * blockDim.x + threadIdx.x;
    const float xv = tx[b * S_ + sI];
    const float th = 6.28318530717958647692f * xv;
    float s1, c1;
    sincosf(th, &s1, &c1);
    float sh = s1, ch = c1;
    float acc = fmaf(cc[0], ch, sc[0] * sh);
    #pragma unroll 4
    for (int h = 1; h < NH_; h++) {
        const float cn = ch * c1 - sh * s1;
        const float sn = sh * c1 + ch * s1;
        ch = cn; sh = sn;
        acc = fmaf(cc[h], ch, acc);
        acc = fmaf(sc[h], sh, acc);
    }
    out[b * S_ + sI] = acc;
}

// ---------------- launcher ----------------
extern "C" void kernel_launch(void* const* d_in, const int* in_sizes, int n_in,
                              void* d_out, int out_size) {
    const float* target_x = (const float*)d_in[0];
    const float* z        = (const float*)d_in[1];
    /* d_in[2] = x, unused by the reference */
    const float* emb      = (const float*)d_in[3];
    const float* w_in     = (const float*)d_in[4];
    const float* b_in     = (const float*)d_in[5];
    const float* w_h      = (const float*)d_in[6];
    const float* b_h      = (const float*)d_in[7];
    const float* w_out    = (const float*)d_in[8];
    const float* b_out    = (const float*)d_in[9];
    float* out = (float*)d_out;

    k_zw<<<dim3(HID_ / 256, B_),  256>>>(z, w_in);
    k_ew<<<dim3(HID_ / 256, NH_), 256>>>(emb, w_in, b_in);
    k_h0<<<dim3(HID_ / 256, M_),  256>>>();

    k_gemm<true><<<dim3(HID_ / 128, M_ / 128), 256>>>(0, 1, w_h + 0 * HID_ * HID_, b_h + 0 * HID_);
    k_gemm<true><<<dim3(HID_ / 128, M_ / 128), 256>>>(1, 0, w_h + 1 * HID_ * HID_, b_h + 1 * HID_);
    k_gemm<true><<<dim3(HID_ / 128, M_ / 128), 256>>>(0, 1, w_h + 2 * HID_ * HID_, b_h + 2 * HID_);

    k_coeff<<<M_, 128>>>(1, w_out, b_out);

    k_synth<<<dim3(S_ / 256, B_), 256>>>(target_x, out);
}

// round 6
// speedup vs baseline: 1.6462x; 1.6462x over previous
#include <cuda_runtime.h>
#include <cuda_bf16.h>
#include <math.h>
#include <stdint.h>

#define B_    64
#define S_    4096
#define E_    266
#define HID_  512
#define NH_   128
#define M_    (B_ * NH_)   /* 8192 rows */
#define KC_   32           /* K chunk */
#define NCH_  (HID_ / KC_) /* 16 chunks */
#define SPAD_ 40           /* padded smem row stride in bf16 */

// ---------------- device scratch (no allocations allowed) ----------------
__device__ __align__(16) __nv_bfloat16 g_ahi[2][M_ * HID_];
__device__ __align__(16) __nv_bfloat16 g_alo[2][M_ * HID_];
__device__ __align__(16) __nv_bfloat16 g_wthi[3][HID_ * HID_];  // W^T [n][k], hi part
__device__ __align__(16) __nv_bfloat16 g_wtlo[3][HID_ * HID_];  // W^T [n][k], lo part
__device__ float g_zw[B_ * HID_];
__device__ float g_ew[NH_ * HID_];
__device__ float g_sinc[M_];
__device__ float g_cosc[M_];

__device__ __forceinline__ float silu(float v) { return v / (1.0f + __expf(-v)); }

__device__ __forceinline__ uint32_t smem_u32(const void* p) {
    uint32_t a;
    asm("{ .reg .u64 t; cvta.to.shared.u64 t, %1; cvt.u32.u64 %0, t; }" : "=r"(a) : "l"(p));
    return a;
}
__device__ __forceinline__ void ldsm_x4(uint32_t* r, uint32_t addr) {
    asm volatile("ldmatrix.sync.aligned.m8n8.x4.shared.b16 {%0,%1,%2,%3}, [%4];"
                 : "=r"(r[0]), "=r"(r[1]), "=r"(r[2]), "=r"(r[3]) : "r"(addr));
}
__device__ __forceinline__ void mma_bf16(float* c, const uint32_t* a, const uint32_t* b) {
    asm volatile("mma.sync.aligned.m16n8k16.row.col.f32.bf16.bf16.f32 "
                 "{%0,%1,%2,%3}, {%4,%5,%6,%7}, {%8,%9}, {%0,%1,%2,%3};"
                 : "+f"(c[0]), "+f"(c[1]), "+f"(c[2]), "+f"(c[3])
                 : "r"(a[0]), "r"(a[1]), "r"(a[2]), "r"(a[3]), "r"(b[0]), "r"(b[1]));
}

// ---------------- weight prep: transpose + bf16 hi/lo split ----------------
__global__ void k_wprep(const float* __restrict__ w_h) {
    __shared__ float t[32][33];
    const int l = blockIdx.z;
    const int k0 = blockIdx.y * 32, n0 = blockIdx.x * 32;
    const float* W = w_h + (size_t)l * HID_ * HID_;
    for (int i = threadIdx.y; i < 32; i += 8)
        t[i][threadIdx.x] = W[(size_t)(k0 + i) * HID_ + n0 + threadIdx.x];
    __syncthreads();
    for (int i = threadIdx.y; i < 32; i += 8) {
        const float v = t[threadIdx.x][i];
        const __nv_bfloat16 hi = __float2bfloat16(v);
        const __nv_bfloat16 lo = __float2bfloat16(v - __bfloat162float(hi));
        g_wthi[l][(size_t)(n0 + i) * HID_ + k0 + threadIdx.x] = hi;
        g_wtlo[l][(size_t)(n0 + i) * HID_ + k0 + threadIdx.x] = lo;
    }
}

// ---------------- z @ w_in : (64 x 266) @ (266 x 512) ----------------
__global__ void k_zw(const float* __restrict__ z, const float* __restrict__ w_in) {
    __shared__ float zr[E_];
    const int b = blockIdx.y;
    for (int e = threadIdx.x; e < E_; e += blockDim.x) zr[e] = z[b * E_ + e];
    __syncthreads();
    const int d = blockIdx.x * blockDim.x + threadIdx.x;
    float acc = 0.f;
    #pragma unroll 2
    for (int e = 0; e < E_; e++) acc = fmaf(zr[e], __ldg(w_in + e * HID_ + d), acc);
    g_zw[b * HID_ + d] = acc;
}

// ---------------- emb @ w_in + b_in ----------------
__global__ void k_ew(const float* __restrict__ emb, const float* __restrict__ w_in,
                     const float* __restrict__ b_in) {
    __shared__ float er[E_];
    const int h = blockIdx.y;
    for (int e = threadIdx.x; e < E_; e += blockDim.x) er[e] = emb[h * E_ + e];
    __syncthreads();
    const int d = blockIdx.x * blockDim.x + threadIdx.x;
    float acc = b_in[d];
    #pragma unroll 2
    for (int e = 0; e < E_; e++) acc = fmaf(er[e], __ldg(w_in + e * HID_ + d), acc);
    g_ew[h * HID_ + d] = acc;
}

// ---------------- h0 = silu(zw[b] + ew[h]) -> bf16 hi/lo ----------------
__global__ void k_h0() {
    const int row = blockIdx.y;
    const int d = blockIdx.x * blockDim.x + threadIdx.x;
    const int b = row >> 7;
    const int h = row & (NH_ - 1);
    const float v = silu(g_zw[b * HID_ + d] + g_ew[h * HID_ + d]);
    const __nv_bfloat16 hi = __float2bfloat16(v);
    const __nv_bfloat16 lo = __float2bfloat16(v - __bfloat162float(hi));
    g_ahi[0][(size_t)row * HID_ + d] = hi;
    g_alo[0][(size_t)row * HID_ + d] = lo;
}

// ---------------- mma.sync split-bf16 GEMM layer ----------------
// g_a*[dst] = silu( (g_ahi[src]+g_alo[src]) @ W_layer + bias ), split to hi/lo.
// 3-term split: Ahi*Bhi + Ahi*Blo + Alo*Bhi, fp32 accum on tensor pipe.
__global__ void __launch_bounds__(256, 2) k_mma_gemm(int layer, int src, int dst,
                                                     const float* __restrict__ bias) {
    __shared__ __align__(16) __nv_bfloat16 sAh[128][SPAD_];
    __shared__ __align__(16) __nv_bfloat16 sAl[128][SPAD_];
    __shared__ __align__(16) __nv_bfloat16 sBh[128][SPAD_];
    __shared__ __align__(16) __nv_bfloat16 sBl[128][SPAD_];

    const int tid = threadIdx.x;
    const int wid = tid >> 5;
    const int lane = tid & 31;
    const int wm = wid & 1;       // 2 warp-rows of 64
    const int wn = wid >> 1;      // 4 warp-cols of 32
    const int m0 = blockIdx.y * 128;
    const int n0 = blockIdx.x * 128;

    const __nv_bfloat16* __restrict__ Ahi  = g_ahi[src];
    const __nv_bfloat16* __restrict__ Alo  = g_alo[src];
    const __nv_bfloat16* __restrict__ Wthi = g_wthi[layer];
    const __nv_bfloat16* __restrict__ Wtlo = g_wtlo[layer];
    __nv_bfloat16* __restrict__ Dhi = g_ahi[dst];
    __nv_bfloat16* __restrict__ Dlo = g_alo[dst];

    float acc[4][4][4];
    #pragma unroll
    for (int i = 0; i < 4; i++)
        #pragma unroll
        for (int j = 0; j < 4; j++)
            #pragma unroll
            for (int q = 0; q < 4; q++) acc[i][j][q] = 0.f;

    // ldmatrix per-thread base offsets
    const int arow = wm * 64 + (lane & 15);        // + mt*16
    const int acol = (lane >> 4) << 3;             // 0/8, + ks*16
    const int brow = wn * 32 + ((lane >> 4) & 1) * 8 + (lane & 7);  // + ntpair*16
    const int bcol = ((lane >> 3) & 1) * 8;        // + ks*16

    const uint32_t sAh0 = smem_u32(&sAh[0][0]);
    const uint32_t sAl0 = smem_u32(&sAl[0][0]);
    const uint32_t sBh0 = smem_u32(&sBh[0][0]);
    const uint32_t sBl0 = smem_u32(&sBl[0][0]);

    for (int c = 0; c < NCH_; c++) {
        const int k0 = c * KC_;
        // stage: 4 tensors, 128 rows x 32 bf16 each; uint64 = 4 bf16
        #pragma unroll
        for (int i = 0; i < 4; i++) {
            const int idx = tid + i * 256;     // 0..1023
            const int r = idx >> 3;
            const int c8 = idx & 7;
            const size_t ga = (size_t)(m0 + r) * HID_ + k0 + c8 * 4;
            const size_t gb = (size_t)(n0 + r) * HID_ + k0 + c8 * 4;
            *(uint64_t*)&sAh[r][c8 * 4] = *(const uint64_t*)(Ahi + ga);
            *(uint64_t*)&sAl[r][c8 * 4] = *(const uint64_t*)(Alo + ga);
            *(uint64_t*)&sBh[r][c8 * 4] = *(const uint64_t*)(Wthi + gb);
            *(uint64_t*)&sBl[r][c8 * 4] = *(const uint64_t*)(Wtlo + gb);
        }
        __syncthreads();

        #pragma unroll
        for (int ks = 0; ks < 2; ks++) {
            const int kc = ks * 16;
            uint32_t bh[8], bl[8];
            #pragma unroll
            for (int np = 0; np < 2; np++) {
                const uint32_t bo = (uint32_t)((brow + np * 16) * SPAD_ + bcol + kc) * 2;
                ldsm_x4(bh + np * 4, sBh0 + bo);
                ldsm_x4(bl + np * 4, sBl0 + bo);
            }
            #pragma unroll
            for (int mt = 0; mt < 4; mt++) {
                const uint32_t ao = (uint32_t)((arow + mt * 16) * SPAD_ + acol + kc) * 2;
                uint32_t ah[4], al[4];
                ldsm_x4(ah, sAh0 + ao);
                ldsm_x4(al, sAl0 + ao);
                #pragma unroll
                for (int nt = 0; nt < 4; nt++) {
                    mma_bf16(acc[mt][nt], ah, bh + nt * 2);
                    mma_bf16(acc[mt][nt], ah, bl + nt * 2);
                    mma_bf16(acc[mt][nt], al, bh + nt * 2);
                }
            }
        }
        __syncthreads();
    }

    // epilogue: bias + silu + hi/lo split, bf162 stores
    const int g = lane >> 2;
    const int cpair = (lane & 3) * 2;
    #pragma unroll
    for (int mt = 0; mt < 4; mt++) {
        #pragma unroll
        for (int nt = 0; nt < 4; nt++) {
            const int row = m0 + wm * 64 + mt * 16 + g;
            const int col = n0 + wn * 32 + nt * 8 + cpair;
            const float b0 = __ldg(bias + col);
            const float b1 = __ldg(bias + col + 1);
            #pragma unroll
            for (int half = 0; half < 2; half++) {
                const int r = row + half * 8;
                float v0 = acc[mt][nt][half * 2 + 0] + b0;
                float v1 = acc[mt][nt][half * 2 + 1] + b1;
                v0 = silu(v0);
                v1 = silu(v1);
                const __nv_bfloat16 h0 = __float2bfloat16(v0);
                const __nv_bfloat16 h1 = __float2bfloat16(v1);
                const __nv_bfloat16 l0 = __float2bfloat16(v0 - __bfloat162float(h0));
                const __nv_bfloat16 l1 = __float2bfloat16(v1 - __bfloat162float(h1));
                __nv_bfloat162 ph, pl;
                ph.x = h0; ph.y = h1;
                pl.x = l0; pl.y = l1;
                *(__nv_bfloat162*)(Dhi + (size_t)r * HID_ + col) = ph;
                *(__nv_bfloat162*)(Dlo + (size_t)r * HID_ + col) = pl;
            }
        }
    }
}

// ---------------- final projection: coeffs = H @ w_out + b_out ----------------
__global__ void k_coeff(int src, const float* __restrict__ w_out,
                        const float* __restrict__ b_out) {
    const int row = blockIdx.x;
    const __nv_bfloat16* hp = g_ahi[src] + (size_t)row * HID_;
    const __nv_bfloat16* lp = g_alo[src] + (size_t)row * HID_;
    float s = 0.f, c = 0.f;
    for (int k = threadIdx.x; k < HID_; k += 128) {
        const float a = __bfloat162float(hp[k]) + __bfloat162float(lp[k]);
        s = fmaf(a, w_out[2 * k + 0], s);
        c = fmaf(a, w_out[2 * k + 1], c);
    }
    #pragma unroll
    for (int o = 16; o > 0; o >>= 1) {
        s += __shfl_down_sync(0xffffffffu, s, o);
        c += __shfl_down_sync(0xffffffffu, c, o);
    }
    __shared__ float ss[4], cs[4];
    const int w = threadIdx.x >> 5;
    if ((threadIdx.x & 31) == 0) { ss[w] = s; cs[w] = c; }
    __syncthreads();
    if (threadIdx.x == 0) {
        g_sinc[row] = ss[0] + ss[1] + ss[2] + ss[3] + b_out[0];
        g_cosc[row] = cs[0] + cs[1] + cs[2] + cs[3] + b_out[1];
    }
}

// ---------------- synthesis with integer-frequency recurrence ----------------
__global__ void k_synth(const float* __restrict__ tx, float* __restrict__ out) {
    __shared__ float sc[NH_], cc[NH_];
    const int b = blockIdx.y;
    if (threadIdx.x < NH_) {
        sc[threadIdx.x] = g_sinc[b * NH_ + threadIdx.x];
        cc[threadIdx.x] = g_cosc[b * NH_ + threadIdx.x];
    }
    __syncthreads();
    const int sI = blockIdx.x * blockDim.x + threadIdx.x;
    const float xv = tx[b * S_ + sI];
    const float th = 6.28318530717958647692f * xv;
    float s1, c1;
    sincosf(th, &s1, &c1);
    float sh = s1, ch = c1;
    float acc = fmaf(cc[0], ch, sc[0] * sh);
    #pragma unroll 4
    for (int h = 1; h < NH_; h++) {
        const float cn = ch * c1 - sh * s1;
        const float sn = sh * c1 + ch * s1;
        ch = cn; sh = sn;
        acc = fmaf(cc[h], ch, acc);
        acc = fmaf(sc[h], sh, acc);
    }
    out[b * S_ + sI] = acc;
}

// ---------------- launcher ----------------
extern "C" void kernel_launch(void* const* d_in, const int* in_sizes, int n_in,
                              void* d_out, int out_size) {
    const float* target_x = (const float*)d_in[0];
    const float* z        = (const float*)d_in[1];
    /* d_in[2] = x, unused by the reference */
    const float* emb      = (const float*)d_in[3];
    const float* w_in     = (const float*)d_in[4];
    const float* b_in     = (const float*)d_in[5];
    const float* w_h      = (const float*)d_in[6];
    const float* b_h      = (const float*)d_in[7];
    const float* w_out    = (const float*)d_in[8];
    const float* b_out    = (const float*)d_in[9];
    float* out = (float*)d_out;

    k_wprep<<<dim3(16, 16, 3), dim3(32, 8)>>>(w_h);
    k_zw<<<dim3(HID_ / 256, B_),  256>>>(z, w_in);
    k_ew<<<dim3(HID_ / 256, NH_), 256>>>(emb, w_in, b_in);
    k_h0<<<dim3(HID_ / 256, M_),  256>>>();

    k_mma_gemm<<<dim3(4, 64), 256>>>(0, 0, 1, b_h + 0 * HID_);
    k_mma_gemm<<<dim3(4, 64), 256>>>(1, 1, 0, b_h + 1 * HID_);
    k_mma_gemm<<<dim3(4, 64), 256>>>(2, 0, 1, b_h + 2 * HID_);

    k_coeff<<<M_, 128>>>(1, w_out, b_out);
    k_synth<<<dim3(S_ / 256, B_), 256>>>(target_x, out);
}

// round 7
// speedup vs baseline: 1.8976x; 1.1527x over previous
#include <cuda_runtime.h>
#include <cuda_bf16.h>
#include <math.h>
#include <stdint.h>

#define B_    64
#define S_    4096
#define E_    266
#define HID_  512
#define NH_   128
#define M_    (B_ * NH_)   /* 8192 rows */
#define KC_   32           /* K chunk */
#define NCH_  (HID_ / KC_) /* 16 chunks */
#define SPAD_ 40           /* padded smem row stride in bf16 */

/* dynamic smem stage layout (bytes) */
#define T_BYTES   (128 * SPAD_ * 2)       /* 10240 per tensor */
#define OFF_AH    0
#define OFF_AL    (1 * T_BYTES)
#define OFF_BH    (2 * T_BYTES)
#define OFF_BL    (3 * T_BYTES)
#define STAGE_B   (4 * T_BYTES)           /* 40960 */
#define SMEM_DYN  (2 * STAGE_B)           /* 81920 */

// ---------------- device scratch (no allocations allowed) ----------------
__device__ __align__(16) __nv_bfloat16 g_ahi[2][M_ * HID_];
__device__ __align__(16) __nv_bfloat16 g_alo[2][M_ * HID_];
__device__ __align__(16) __nv_bfloat16 g_wthi[3][HID_ * HID_];  // W^T [n][k], hi
__device__ __align__(16) __nv_bfloat16 g_wtlo[3][HID_ * HID_];  // W^T [n][k], lo
__device__ float g_zw[B_ * HID_];
__device__ float g_ew[NH_ * HID_];
__device__ float g_sinc[M_];
__device__ float g_cosc[M_];

__device__ __forceinline__ float silu(float v) {
    return __fdividef(v, 1.0f + __expf(-v));
}
__device__ __forceinline__ uint32_t smem_u32(const void* p) {
    uint32_t a;
    asm("{ .reg .u64 t; cvta.to.shared.u64 t, %1; cvt.u32.u64 %0, t; }" : "=r"(a) : "l"(p));
    return a;
}
__device__ __forceinline__ void cp16(uint32_t sm, const void* g) {
    asm volatile("cp.async.cg.shared.global [%0], [%1], 16;" :: "r"(sm), "l"(g));
}
__device__ __forceinline__ void cp_commit() {
    asm volatile("cp.async.commit_group;" ::: "memory");
}
template <int N>
__device__ __forceinline__ void cp_wait() {
    asm volatile("cp.async.wait_group %0;" :: "n"(N) : "memory");
}
__device__ __forceinline__ void ldsm_x4(uint32_t* r, uint32_t addr) {
    asm volatile("ldmatrix.sync.aligned.m8n8.x4.shared.b16 {%0,%1,%2,%3}, [%4];"
                 : "=r"(r[0]), "=r"(r[1]), "=r"(r[2]), "=r"(r[3]) : "r"(addr));
}
__device__ __forceinline__ void mma_bf16(float* c, const uint32_t* a, const uint32_t* b) {
    asm volatile("mma.sync.aligned.m16n8k16.row.col.f32.bf16.bf16.f32 "
                 "{%0,%1,%2,%3}, {%4,%5,%6,%7}, {%8,%9}, {%0,%1,%2,%3};"
                 : "+f"(c[0]), "+f"(c[1]), "+f"(c[2]), "+f"(c[3])
                 : "r"(a[0]), "r"(a[1]), "r"(a[2]), "r"(a[3]), "r"(b[0]), "r"(b[1]));
}
__device__ __forceinline__ void split_store(char* sm_hi, char* sm_lo, int off,
                                            float v0, float v1, float v2, float v3) {
    const __nv_bfloat16 h0 = __float2bfloat16(v0), h1 = __float2bfloat16(v1);
    const __nv_bfloat16 h2 = __float2bfloat16(v2), h3 = __float2bfloat16(v3);
    const __nv_bfloat16 l0 = __float2bfloat16(v0 - __bfloat162float(h0));
    const __nv_bfloat16 l1 = __float2bfloat16(v1 - __bfloat162float(h1));
    const __nv_bfloat16 l2 = __float2bfloat16(v2 - __bfloat162float(h2));
    const __nv_bfloat16 l3 = __float2bfloat16(v3 - __bfloat162float(h3));
    ushort4 ph, pl;
    ph.x = __bfloat16_as_ushort(h0); ph.y = __bfloat16_as_ushort(h1);
    ph.z = __bfloat16_as_ushort(h2); ph.w = __bfloat16_as_ushort(h3);
    pl.x = __bfloat16_as_ushort(l0); pl.y = __bfloat16_as_ushort(l1);
    pl.z = __bfloat16_as_ushort(l2); pl.w = __bfloat16_as_ushort(l3);
    *(ushort4*)(sm_hi + off) = ph;
    *(ushort4*)(sm_lo + off) = pl;
}

// ---------------- weight prep: transpose + bf16 hi/lo split ----------------
__global__ void k_wprep(const float* __restrict__ w_h) {
    __shared__ float t[32][33];
    const int l = blockIdx.z;
    const int k0 = blockIdx.y * 32, n0 = blockIdx.x * 32;
    const float* W = w_h + (size_t)l * HID_ * HID_;
    for (int i = threadIdx.y; i < 32; i += 8)
        t[i][threadIdx.x] = W[(size_t)(k0 + i) * HID_ + n0 + threadIdx.x];
    __syncthreads();
    for (int i = threadIdx.y; i < 32; i += 8) {
        const float v = t[threadIdx.x][i];
        const __nv_bfloat16 hi = __float2bfloat16(v);
        const __nv_bfloat16 lo = __float2bfloat16(v - __bfloat162float(hi));
        g_wthi[l][(size_t)(n0 + i) * HID_ + k0 + threadIdx.x] = hi;
        g_wtlo[l][(size_t)(n0 + i) * HID_ + k0 + threadIdx.x] = lo;
    }
}

// ---------------- z @ w_in : (64 x 266) @ (266 x 512) ----------------
__global__ void k_zw(const float* __restrict__ z, const float* __restrict__ w_in) {
    __shared__ float zr[E_];
    const int b = blockIdx.y;
    for (int e = threadIdx.x; e < E_; e += blockDim.x) zr[e] = z[b * E_ + e];
    __syncthreads();
    const int d = blockIdx.x * blockDim.x + threadIdx.x;
    float acc = 0.f;
    #pragma unroll 2
    for (int e = 0; e < E_; e++) acc = fmaf(zr[e], __ldg(w_in + e * HID_ + d), acc);
    g_zw[b * HID_ + d] = acc;
}

// ---------------- emb @ w_in + b_in ----------------
__global__ void k_ew(const float* __restrict__ emb, const float* __restrict__ w_in,
                     const float* __restrict__ b_in) {
    __shared__ float er[E_];
    const int h = blockIdx.y;
    for (int e = threadIdx.x; e < E_; e += blockDim.x) er[e] = emb[h * E_ + e];
    __syncthreads();
    const int d = blockIdx.x * blockDim.x + threadIdx.x;
    float acc = b_in[d];
    #pragma unroll 2
    for (int e = 0; e < E_; e++) acc = fmaf(er[e], __ldg(w_in + e * HID_ + d), acc);
    g_ew[h * HID_ + d] = acc;
}

// ---------------- init coeff accumulators with output bias ----------------
__global__ void k_cinit(const float* __restrict__ b_out) {
    const int i = blockIdx.x * 256 + threadIdx.x;
    g_sinc[i] = b_out[0];
    g_cosc[i] = b_out[1];
}

// ---------------- fused MLP GEMM ----------------
// MODE 0: middle layer  (A async from g_a*[src], writes hi/lo to g_a*[dst])
// MODE 1: first layer   (A staged synchronously = silu(zw[b]+ew[h]) split, B async)
// MODE 2: last layer    (A async, epilogue fused with w_out projection -> atomics)
template <int MODE>
__global__ void __launch_bounds__(256, 2) k_mma_gemm(int layer, int src, int dst,
                                                     const float* __restrict__ bias,
                                                     const float* __restrict__ w_out) {
    extern __shared__ char smem[];
    const int tid = threadIdx.x;
    const int wid = tid >> 5;
    const int lane = tid & 31;
    const int wm = wid & 1;
    const int wn = wid >> 1;
    const int m0 = blockIdx.y * 128;
    const int n0 = blockIdx.x * 128;

    const __nv_bfloat16* __restrict__ Ahi  = g_ahi[src];
    const __nv_bfloat16* __restrict__ Alo  = g_alo[src];
    const __nv_bfloat16* __restrict__ Wthi = g_wthi[layer];
    const __nv_bfloat16* __restrict__ Wtlo = g_wtlo[layer];
    __nv_bfloat16* __restrict__ Dhi = g_ahi[dst];
    __nv_bfloat16* __restrict__ Dlo = g_alo[dst];

    const uint32_t smb = smem_u32(smem);

    // ---- staging helper (issues cp.async; MODE 1 also fills A synchronously) ----
    auto stage_load = [&](int c, int buf) {
        const int k0 = c * KC_;
        char* sb = smem + buf * STAGE_B;
        const uint32_t sbu = smb + buf * STAGE_B;
        if (MODE != 1) {
            #pragma unroll
            for (int i = 0; i < 8; i++) {
                const int idx = tid + i * 256;       // 0..2047
                const int t = idx >> 9;              // 0:Ah 1:Al 2:Bh 3:Bl
                const int j = idx & 511;
                const int r = j >> 2;
                const int c16 = j & 3;
                const uint32_t sm = sbu + t * T_BYTES + r * (SPAD_ * 2) + c16 * 16;
                const __nv_bfloat16* gp;
                if (t == 0)      gp = Ahi  + (size_t)(m0 + r) * HID_ + k0 + c16 * 8;
                else if (t == 1) gp = Alo  + (size_t)(m0 + r) * HID_ + k0 + c16 * 8;
                else if (t == 2) gp = Wthi + (size_t)(n0 + r) * HID_ + k0 + c16 * 8;
                else             gp = Wtlo + (size_t)(n0 + r) * HID_ + k0 + c16 * 8;
                cp16(sm, gp);
            }
        } else {
            #pragma unroll
            for (int i = 0; i < 4; i++) {
                const int idx = tid + i * 256;       // 0..1023
                const int t = idx >> 9;              // 0:Bh 1:Bl
                const int j = idx & 511;
                const int r = j >> 2;
                const int c16 = j & 3;
                const uint32_t sm = sbu + (t ? OFF_BL : OFF_BH) + r * (SPAD_ * 2) + c16 * 16;
                const __nv_bfloat16* gp = (t ? Wtlo : Wthi) + (size_t)(n0 + r) * HID_ + k0 + c16 * 8;
                cp16(sm, gp);
            }
            // A = silu(zw[b] + ew[h]), split hi/lo, 4 floats per thread-iter
            #pragma unroll
            for (int i = 0; i < 4; i++) {
                const int idx = tid + i * 256;       // 0..1023
                const int r = idx >> 3;
                const int q = idx & 7;               // 4-float group
                const int row = m0 + r;
                const int bb = row >> 7;
                const int hh = row & (NH_ - 1);
                const float4 zv = *(const float4*)(g_zw + bb * HID_ + k0 + q * 4);
                const float4 ev = *(const float4*)(g_ew + hh * HID_ + k0 + q * 4);
                const float v0 = silu(zv.x + ev.x);
                const float v1 = silu(zv.y + ev.y);
                const float v2 = silu(zv.z + ev.z);
                const float v3 = silu(zv.w + ev.w);
                const int off = r * (SPAD_ * 2) + q * 8;
                split_store(sb + OFF_AH, sb + OFF_AL, off, v0, v1, v2, v3);
            }
        }
    };

    float acc[4][4][4];
    #pragma unroll
    for (int i = 0; i < 4; i++)
        #pragma unroll
        for (int j = 0; j < 4; j++)
            #pragma unroll
            for (int q = 0; q < 4; q++) acc[i][j][q] = 0.f;

    const int arow = wm * 64 + (lane & 15);
    const int acol = (lane >> 4) << 3;
    const int brow = wn * 32 + ((lane >> 4) & 1) * 8 + (lane & 7);
    const int bcol = ((lane >> 3) & 1) * 8;

    stage_load(0, 0);
    cp_commit();

    for (int c = 0; c < NCH_; c++) {
        if (c + 1 < NCH_) {
            stage_load(c + 1, (c + 1) & 1);
            cp_commit();
            cp_wait<1>();
        } else {
            cp_wait<0>();
        }
        __syncthreads();

        const uint32_t sbu = smb + (c & 1) * STAGE_B;
        const uint32_t aH = sbu + OFF_AH, aL = sbu + OFF_AL;
        const uint32_t bH = sbu + OFF_BH, bL = sbu + OFF_BL;

        #pragma unroll
        for (int ks = 0; ks < 2; ks++) {
            const int kc = ks * 16;
            uint32_t bh[8], bl[8];
            #pragma unroll
            for (int np = 0; np < 2; np++) {
                const uint32_t bo = (uint32_t)((brow + np * 16) * SPAD_ + bcol + kc) * 2;
                ldsm_x4(bh + np * 4, bH + bo);
                ldsm_x4(bl + np * 4, bL + bo);
            }
            #pragma unroll
            for (int mt = 0; mt < 4; mt++) {
                const uint32_t ao = (uint32_t)((arow + mt * 16) * SPAD_ + acol + kc) * 2;
                uint32_t ah[4], al[4];
                ldsm_x4(ah, aH + ao);
                ldsm_x4(al, aL + ao);
                #pragma unroll
                for (int nt = 0; nt < 4; nt++) {
                    mma_bf16(acc[mt][nt], ah, bh + nt * 2);
                    mma_bf16(acc[mt][nt], ah, bl + nt * 2);
                    mma_bf16(acc[mt][nt], al, bh + nt * 2);
                }
            }
        }
        __syncthreads();
    }

    // ---- epilogue ----
    const int g = lane >> 2;
    const int cpair = (lane & 3) * 2;

    if (MODE != 2) {
        #pragma unroll
        for (int mt = 0; mt < 4; mt++) {
            #pragma unroll
            for (int nt = 0; nt < 4; nt++) {
                const int row = m0 + wm * 64 + mt * 16 + g;
                const int col = n0 + wn * 32 + nt * 8 + cpair;
                const float b0 = __ldg(bias + col);
                const float b1 = __ldg(bias + col + 1);
                #pragma unroll
                for (int half = 0; half < 2; half++) {
                    const int r = row + half * 8;
                    const float v0 = silu(acc[mt][nt][half * 2 + 0] + b0);
                    const float v1 = silu(acc[mt][nt][half * 2 + 1] + b1);
                    const __nv_bfloat16 h0 = __float2bfloat16(v0);
                    const __nv_bfloat16 h1 = __float2bfloat16(v1);
                    const __nv_bfloat16 l0 = __float2bfloat16(v0 - __bfloat162float(h0));
                    const __nv_bfloat16 l1 = __float2bfloat16(v1 - __bfloat162float(h1));
                    __nv_bfloat162 ph, pl;
                    ph.x = h0; ph.y = h1;
                    pl.x = l0; pl.y = l1;
                    *(__nv_bfloat162*)(Dhi + (size_t)r * HID_ + col) = ph;
                    *(__nv_bfloat162*)(Dlo + (size_t)r * HID_ + col) = pl;
                }
            }
        }
    } else {
        // fused coeff projection: s/c = sum_col silu(v+bias) * w_out[col][0/1]
        #pragma unroll
        for (int mt = 0; mt < 4; mt++) {
            #pragma unroll
            for (int half = 0; half < 2; half++) {
                float s = 0.f, cs = 0.f;
                #pragma unroll
                for (int nt = 0; nt < 4; nt++) {
                    const int col = n0 + wn * 32 + nt * 8 + cpair;
                    const float b0 = __ldg(bias + col);
                    const float b1 = __ldg(bias + col + 1);
                    const float v0 = silu(acc[mt][nt][half * 2 + 0] + b0);
                    const float v1 = silu(acc[mt][nt][half * 2 + 1] + b1);
                    s  = fmaf(v0, __ldg(w_out + 2 * col + 0), s);
                    cs = fmaf(v0, __ldg(w_out + 2 * col + 1), cs);
                    s  = fmaf(v1, __ldg(w_out + 2 * col + 2), s);
                    cs = fmaf(v1, __ldg(w_out + 2 * col + 3), cs);
                }
                s  += __shfl_xor_sync(0xffffffffu, s, 1);
                s  += __shfl_xor_sync(0xffffffffu, s, 2);
                cs += __shfl_xor_sync(0xffffffffu, cs, 1);
                cs += __shfl_xor_sync(0xffffffffu, cs, 2);
                if ((lane & 3) == 0) {
                    const int row = m0 + wm * 64 + mt * 16 + g + half * 8;
                    atomicAdd(&g_sinc[row], s);
                    atomicAdd(&g_cosc[row], cs);
                }
            }
        }
    }
}

// ---------------- synthesis with integer-frequency recurrence ----------------
__global__ void k_synth(const float* __restrict__ tx, float* __restrict__ out) {
    __shared__ float sc[NH_], cc[NH_];
    const int b = blockIdx.y;
    if (threadIdx.x < NH_) {
        sc[threadIdx.x] = g_sinc[b * NH_ + threadIdx.x];
        cc[threadIdx.x] = g_cosc[b * NH_ + threadIdx.x];
    }
    __syncthreads();
    const int sI = blockIdx.x * blockDim.x + threadIdx.x;
    const float xv = tx[b * S_ + sI];
    const float th = 6.28318530717958647692f * xv;
    float s1, c1;
    sincosf(th, &s1, &c1);
    float sh = s1, ch = c1;
    float acc = fmaf(cc[0], ch, sc[0] * sh);
    #pragma unroll 4
    for (int h = 1; h < NH_; h++) {
        const float cn = ch * c1 - sh * s1;
        const float sn = sh * c1 + ch * s1;
        ch = cn; sh = sn;
        acc = fmaf(cc[h], ch, acc);
        acc = fmaf(sc[h], sh, acc);
    }
    out[b * S_ + sI] = acc;
}

// ---------------- launcher ----------------
extern "C" void kernel_launch(void* const* d_in, const int* in_sizes, int n_in,
                              void* d_out, int out_size) {
    const float* target_x = (const float*)d_in[0];
    const float* z        = (const float*)d_in[1];
    /* d_in[2] = x, unused by the reference */
    const float* emb      = (const float*)d_in[3];
    const float* w_in     = (const float*)d_in[4];
    const float* b_in     = (const float*)d_in[5];
    const float* w_h      = (const float*)d_in[6];
    const float* b_h      = (const float*)d_in[7];
    const float* w_out    = (const float*)d_in[8];
    const float* b_out    = (const float*)d_in[9];
    float* out = (float*)d_out;

    cudaFuncSetAttribute(k_mma_gemm<0>, cudaFuncAttributeMaxDynamicSharedMemorySize, SMEM_DYN);
    cudaFuncSetAttribute(k_mma_gemm<1>, cudaFuncAttributeMaxDynamicSharedMemorySize, SMEM_DYN);
    cudaFuncSetAttribute(k_mma_gemm<2>, cudaFuncAttributeMaxDynamicSharedMemorySize, SMEM_DYN);

    k_wprep<<<dim3(16, 16, 3), dim3(32, 8)>>>(w_h);
    k_zw<<<dim3(HID_ / 256, B_),  256>>>(z, w_in);
    k_ew<<<dim3(HID_ / 256, NH_), 256>>>(emb, w_in, b_in);
    k_cinit<<<M_ / 256, 256>>>(b_out);

    k_mma_gemm<1><<<dim3(4, 64), 256, SMEM_DYN>>>(0, 0, 0, b_h + 0 * HID_, w_out);
    k_mma_gemm<0><<<dim3(4, 64), 256, SMEM_DYN>>>(1, 0, 1, b_h + 1 * HID_, w_out);
    k_mma_gemm<2><<<dim3(4, 64), 256, SMEM_DYN>>>(2, 1, 0, b_h + 2 * HID_, w_out);

    k_synth<<<dim3(S_ / 256, B_), 256>>>(target_x, out);
}

// round 8
// speedup vs baseline: 2.0507x; 1.0806x over previous
#include <cuda_runtime.h>
#include <cuda_bf16.h>
#include <math.h>
#include <stdint.h>

#define B_    64
#define S_    4096
#define E_    266
#define HID_  512
#define NH_   128
#define M_    (B_ * NH_)   /* 8192 rows */
#define KC_   32           /* K chunk */
#define NCH_  (HID_ / KC_) /* 16 chunks */
#define SPAD_ 40           /* padded smem row stride in bf16 */
#define BM_   256          /* CTA tile M */
#define BN_   128          /* CTA tile N */

/* dynamic smem stage layout (bytes): A 256 rows, B 128 rows, hi+lo */
#define ROWB_     (SPAD_ * 2)                 /* 80 B per row */
#define OFF_AH    0
#define OFF_AL    (BM_ * ROWB_)               /* 20480 */
#define OFF_BH    (2 * BM_ * ROWB_)           /* 40960 */
#define OFF_BL    (2 * BM_ * ROWB_ + BN_ * ROWB_)  /* 51200 */
#define STAGE_B   (2 * BM_ * ROWB_ + 2 * BN_ * ROWB_) /* 61440 */
#define SMEM_DYN  (2 * STAGE_B)               /* 122880 */

// ---------------- device scratch (no allocations allowed) ----------------
__device__ __align__(16) __nv_bfloat16 g_ahi[2][M_ * HID_];
__device__ __align__(16) __nv_bfloat16 g_alo[2][M_ * HID_];
__device__ __align__(16) __nv_bfloat16 g_wthi[3][HID_ * HID_];  // W^T [n][k], hi
__device__ __align__(16) __nv_bfloat16 g_wtlo[3][HID_ * HID_];  // W^T [n][k], lo
__device__ float g_zw[B_ * HID_];
__device__ float g_ew[NH_ * HID_];
__device__ float g_sinc[M_];
__device__ float g_cosc[M_];

__device__ __forceinline__ float silu(float v) {
    return __fdividef(v, 1.0f + __expf(-v));
}
__device__ __forceinline__ uint32_t smem_u32(const void* p) {
    uint32_t a;
    asm("{ .reg .u64 t; cvta.to.shared.u64 t, %1; cvt.u32.u64 %0, t; }" : "=r"(a) : "l"(p));
    return a;
}
__device__ __forceinline__ void cp16(uint32_t sm, const void* g) {
    asm volatile("cp.async.cg.shared.global [%0], [%1], 16;" :: "r"(sm), "l"(g));
}
__device__ __forceinline__ void cp_commit() {
    asm volatile("cp.async.commit_group;" ::: "memory");
}
template <int N>
__device__ __forceinline__ void cp_wait() {
    asm volatile("cp.async.wait_group %0;" :: "n"(N) : "memory");
}
__device__ __forceinline__ void ldsm_x4(uint32_t* r, uint32_t addr) {
    asm volatile("ldmatrix.sync.aligned.m8n8.x4.shared.b16 {%0,%1,%2,%3}, [%4];"
                 : "=r"(r[0]), "=r"(r[1]), "=r"(r[2]), "=r"(r[3]) : "r"(addr));
}
__device__ __forceinline__ void mma_bf16(float* c, const uint32_t* a, const uint32_t* b) {
    asm volatile("mma.sync.aligned.m16n8k16.row.col.f32.bf16.bf16.f32 "
                 "{%0,%1,%2,%3}, {%4,%5,%6,%7}, {%8,%9}, {%0,%1,%2,%3};"
                 : "+f"(c[0]), "+f"(c[1]), "+f"(c[2]), "+f"(c[3])
                 : "r"(a[0]), "r"(a[1]), "r"(a[2]), "r"(a[3]), "r"(b[0]), "r"(b[1]));
}
__device__ __forceinline__ void split_store(char* sm_hi, char* sm_lo, int off,
                                            float v0, float v1, float v2, float v3) {
    const __nv_bfloat16 h0 = __float2bfloat16(v0), h1 = __float2bfloat16(v1);
    const __nv_bfloat16 h2 = __float2bfloat16(v2), h3 = __float2bfloat16(v3);
    const __nv_bfloat16 l0 = __float2bfloat16(v0 - __bfloat162float(h0));
    const __nv_bfloat16 l1 = __float2bfloat16(v1 - __bfloat162float(h1));
    const __nv_bfloat16 l2 = __float2bfloat16(v2 - __bfloat162float(h2));
    const __nv_bfloat16 l3 = __float2bfloat16(v3 - __bfloat162float(h3));
    ushort4 ph, pl;
    ph.x = __bfloat16_as_ushort(h0); ph.y = __bfloat16_as_ushort(h1);
    ph.z = __bfloat16_as_ushort(h2); ph.w = __bfloat16_as_ushort(h3);
    pl.x = __bfloat16_as_ushort(l0); pl.y = __bfloat16_as_ushort(l1);
    pl.z = __bfloat16_as_ushort(l2); pl.w = __bfloat16_as_ushort(l3);
    *(ushort4*)(sm_hi + off) = ph;
    *(ushort4*)(sm_lo + off) = pl;
}

// ---------------- weight prep: transpose + bf16 hi/lo split ----------------
__global__ void k_wprep(const float* __restrict__ w_h) {
    __shared__ float t[32][33];
    const int l = blockIdx.z;
    const int k0 = blockIdx.y * 32, n0 = blockIdx.x * 32;
    const float* W = w_h + (size_t)l * HID_ * HID_;
    for (int i = threadIdx.y; i < 32; i += 8)
        t[i][threadIdx.x] = W[(size_t)(k0 + i) * HID_ + n0 + threadIdx.x];
    __syncthreads();
    for (int i = threadIdx.y; i < 32; i += 8) {
        const float v = t[threadIdx.x][i];
        const __nv_bfloat16 hi = __float2bfloat16(v);
        const __nv_bfloat16 lo = __float2bfloat16(v - __bfloat162float(hi));
        g_wthi[l][(size_t)(n0 + i) * HID_ + k0 + threadIdx.x] = hi;
        g_wtlo[l][(size_t)(n0 + i) * HID_ + k0 + threadIdx.x] = lo;
    }
}

// ---------------- fused prelude: zw, ew(+b_in), coeff-acc init ----------------
// grid (2, 192): y<64 -> z rows, y>=64 -> emb rows (ew adds b_in).
__global__ void k_pre(const float* __restrict__ z, const float* __restrict__ emb,
                      const float* __restrict__ w_in, const float* __restrict__ b_in,
                      const float* __restrict__ b_out) {
    __shared__ float vr[E_];
    const int y = blockIdx.y;
    const bool is_z = (y < B_);
    const int row = is_z ? y : y - B_;
    const float* src = (is_z ? z : emb) + (size_t)row * E_;
    for (int e = threadIdx.x; e < E_; e += blockDim.x) vr[e] = src[e];
    __syncthreads();
    const int d = blockIdx.x * blockDim.x + threadIdx.x;
    float acc = is_z ? 0.f : b_in[d];
    #pragma unroll 2
    for (int e = 0; e < E_; e++) acc = fmaf(vr[e], __ldg(w_in + e * HID_ + d), acc);
    if (is_z) g_zw[row * HID_ + d] = acc;
    else      g_ew[row * HID_ + d] = acc;
    // seed coeff accumulators with output bias (rows 0..15 of the emb half)
    if (!is_z && row < 16) {
        const int idx = row * HID_ + d;   // 16*512 = 8192 = M_
        g_sinc[idx] = b_out[0];
        g_cosc[idx] = b_out[1];
    }
}

// ---------------- fused MLP GEMM (CTA 256x128, warp 64x64) ----------------
// MODE 0: middle layer  (A async from g_a*[src], writes hi/lo to g_a*[dst])
// MODE 1: first layer   (A staged synchronously = silu(zw[b]+ew[h]) split)
// MODE 2: last layer    (A async, epilogue fused with w_out projection -> atomics)
template <int MODE>
__global__ void __launch_bounds__(256, 1) k_mma_gemm(int layer, int src, int dst,
                                                     const float* __restrict__ bias,
                                                     const float* __restrict__ w_out) {
    extern __shared__ char smem[];
    const int tid = threadIdx.x;
    const int wid = tid >> 5;
    const int lane = tid & 31;
    const int wm = wid & 3;        // 4 warp-rows of 64
    const int wn = wid >> 2;       // 2 warp-cols of 64
    const int m0 = blockIdx.y * BM_;
    const int n0 = blockIdx.x * BN_;

    const __nv_bfloat16* __restrict__ Ahi  = g_ahi[src];
    const __nv_bfloat16* __restrict__ Alo  = g_alo[src];
    const __nv_bfloat16* __restrict__ Wthi = g_wthi[layer];
    const __nv_bfloat16* __restrict__ Wtlo = g_wtlo[layer];
    __nv_bfloat16* __restrict__ Dhi = g_ahi[dst];
    __nv_bfloat16* __restrict__ Dlo = g_alo[dst];

    const uint32_t smb = smem_u32(smem);

    auto stage_load = [&](int c, int buf) {
        const int k0 = c * KC_;
        char* sb = smem + buf * STAGE_B;
        const uint32_t sbu = smb + buf * STAGE_B;
        if (MODE != 1) {
            // A hi/lo: 2048 cp16, B hi/lo: 1024 cp16 -> 12 per thread
            #pragma unroll
            for (int i = 0; i < 8; i++) {           // A
                const int idx = tid + i * 256;      // 0..2047
                const int t = idx >> 10;            // 0:Ah 1:Al
                const int j = idx & 1023;
                const int r = j >> 2;               // 0..255
                const int c16 = j & 3;
                const uint32_t sm = sbu + (t ? OFF_AL : OFF_AH) + r * ROWB_ + c16 * 16;
                const __nv_bfloat16* gp = (t ? Alo : Ahi) + (size_t)(m0 + r) * HID_ + k0 + c16 * 8;
                cp16(sm, gp);
            }
            #pragma unroll
            for (int i = 0; i < 4; i++) {           // B
                const int idx = tid + i * 256;      // 0..1023
                const int t = idx >> 9;             // 0:Bh 1:Bl
                const int j = idx & 511;
                const int r = j >> 2;               // 0..127
                const int c16 = j & 3;
                const uint32_t sm = sbu + (t ? OFF_BL : OFF_BH) + r * ROWB_ + c16 * 16;
                const __nv_bfloat16* gp = (t ? Wtlo : Wthi) + (size_t)(n0 + r) * HID_ + k0 + c16 * 8;
                cp16(sm, gp);
            }
        } else {
            #pragma unroll
            for (int i = 0; i < 4; i++) {           // B async
                const int idx = tid + i * 256;
                const int t = idx >> 9;
                const int j = idx & 511;
                const int r = j >> 2;
                const int c16 = j & 3;
                const uint32_t sm = sbu + (t ? OFF_BL : OFF_BH) + r * ROWB_ + c16 * 16;
                const __nv_bfloat16* gp = (t ? Wtlo : Wthi) + (size_t)(n0 + r) * HID_ + k0 + c16 * 8;
                cp16(sm, gp);
            }
            // A = silu(zw[b] + ew[h]) split hi/lo: 256 rows x 32 k
            #pragma unroll
            for (int i = 0; i < 8; i++) {
                const int idx = tid + i * 256;      // 0..2047
                const int r = idx >> 3;             // 0..255
                const int q = idx & 7;
                const int row = m0 + r;
                const int bb = row >> 7;
                const int hh = row & (NH_ - 1);
                const float4 zv = *(const float4*)(g_zw + bb * HID_ + k0 + q * 4);
                const float4 ev = *(const float4*)(g_ew + hh * HID_ + k0 + q * 4);
                const float v0 = silu(zv.x + ev.x);
                const float v1 = silu(zv.y + ev.y);
                const float v2 = silu(zv.z + ev.z);
                const float v3 = silu(zv.w + ev.w);
                split_store(sb + OFF_AH, sb + OFF_AL, r * ROWB_ + q * 8, v0, v1, v2, v3);
            }
        }
    };

    float acc[4][8][4];
    #pragma unroll
    for (int i = 0; i < 4; i++)
        #pragma unroll
        for (int j = 0; j < 8; j++)
            #pragma unroll
            for (int q = 0; q < 4; q++) acc[i][j][q] = 0.f;

    const int arow = wm * 64 + (lane & 15);
    const int acol = (lane >> 4) << 3;
    const int brow = wn * 64 + ((lane >> 4) & 1) * 8 + (lane & 7);
    const int bcol = ((lane >> 3) & 1) * 8;

    stage_load(0, 0);
    cp_commit();

    for (int c = 0; c < NCH_; c++) {
        if (c + 1 < NCH_) {
            stage_load(c + 1, (c + 1) & 1);
            cp_commit();
            cp_wait<1>();
        } else {
            cp_wait<0>();
        }
        __syncthreads();

        const uint32_t sbu = smb + (c & 1) * STAGE_B;
        const uint32_t aH = sbu + OFF_AH, aL = sbu + OFF_AL;
        const uint32_t bH = sbu + OFF_BH, bL = sbu + OFF_BL;

        #pragma unroll
        for (int ks = 0; ks < 2; ks++) {
            const int kc = ks * 16;
            uint32_t bh[16], bl[16];
            #pragma unroll
            for (int np = 0; np < 4; np++) {
                const uint32_t bo = (uint32_t)((brow + np * 16) * SPAD_ + bcol + kc) * 2;
                ldsm_x4(bh + np * 4, bH + bo);
                ldsm_x4(bl + np * 4, bL + bo);
            }
            #pragma unroll
            for (int mt = 0; mt < 4; mt++) {
                const uint32_t ao = (uint32_t)((arow + mt * 16) * SPAD_ + acol + kc) * 2;
                uint32_t ah[4], al[4];
                ldsm_x4(ah, aH + ao);
                ldsm_x4(al, aL + ao);
                #pragma unroll
                for (int nt = 0; nt < 8; nt++) {
                    mma_bf16(acc[mt][nt], ah, bh + nt * 2);
                    mma_bf16(acc[mt][nt], ah, bl + nt * 2);
                    mma_bf16(acc[mt][nt], al, bh + nt * 2);
                }
            }
        }
        __syncthreads();
    }

    // ---- epilogue ----
    const int g = lane >> 2;
    const int cpair = (lane & 3) * 2;

    if (MODE != 2) {
        #pragma unroll
        for (int mt = 0; mt < 4; mt++) {
            #pragma unroll
            for (int nt = 0; nt < 8; nt++) {
                const int row = m0 + wm * 64 + mt * 16 + g;
                const int col = n0 + wn * 64 + nt * 8 + cpair;
                const float b0 = __ldg(bias + col);
                const float b1 = __ldg(bias + col + 1);
                #pragma unroll
                for (int half = 0; half < 2; half++) {
                    const int r = row + half * 8;
                    const float v0 = silu(acc[mt][nt][half * 2 + 0] + b0);
                    const float v1 = silu(acc[mt][nt][half * 2 + 1] + b1);
                    const __nv_bfloat16 h0 = __float2bfloat16(v0);
                    const __nv_bfloat16 h1 = __float2bfloat16(v1);
                    const __nv_bfloat16 l0 = __float2bfloat16(v0 - __bfloat162float(h0));
                    const __nv_bfloat16 l1 = __float2bfloat16(v1 - __bfloat162float(h1));
                    __nv_bfloat162 ph, pl;
                    ph.x = h0; ph.y = h1;
                    pl.x = l0; pl.y = l1;
                    *(__nv_bfloat162*)(Dhi + (size_t)r * HID_ + col) = ph;
                    *(__nv_bfloat162*)(Dlo + (size_t)r * HID_ + col) = pl;
                }
            }
        }
    } else {
        // fused coeff projection: s/c = sum_col silu(v+bias) * w_out[col][0/1]
        #pragma unroll
        for (int mt = 0; mt < 4; mt++) {
            #pragma unroll
            for (int half = 0; half < 2; half++) {
                float s = 0.f, cs = 0.f;
                #pragma unroll
                for (int nt = 0; nt < 8; nt++) {
                    const int col = n0 + wn * 64 + nt * 8 + cpair;
                    const float b0 = __ldg(bias + col);
                    const float b1 = __ldg(bias + col + 1);
                    const float v0 = silu(acc[mt][nt][half * 2 + 0] + b0);
                    const float v1 = silu(acc[mt][nt][half * 2 + 1] + b1);
                    s  = fmaf(v0, __ldg(w_out + 2 * col + 0), s);
                    cs = fmaf(v0, __ldg(w_out + 2 * col + 1), cs);
                    s  = fmaf(v1, __ldg(w_out + 2 * col + 2), s);
                    cs = fmaf(v1, __ldg(w_out + 2 * col + 3), cs);
                }
                s  += __shfl_xor_sync(0xffffffffu, s, 1);
                s  += __shfl_xor_sync(0xffffffffu, s, 2);
                cs += __shfl_xor_sync(0xffffffffu, cs, 1);
                cs += __shfl_xor_sync(0xffffffffu, cs, 2);
                if ((lane & 3) == 0) {
                    const int row = m0 + wm * 64 + mt * 16 + g + half * 8;
                    atomicAdd(&g_sinc[row], s);
                    atomicAdd(&g_cosc[row], cs);
                }
            }
        }
    }
}

// ---------------- synthesis with integer-frequency recurrence ----------------
__global__ void k_synth(const float* __restrict__ tx, float* __restrict__ out) {
    __shared__ float sc[NH_], cc[NH_];
    const int b = blockIdx.y;
    if (threadIdx.x < NH_) {
        sc[threadIdx.x] = g_sinc[b * NH_ + threadIdx.x];
        cc[threadIdx.x] = g_cosc[b * NH_ + threadIdx.x];
    }
    __syncthreads();
    const int sI = blockIdx.x * blockDim.x + threadIdx.x;
    const float xv = tx[b * S_ + sI];
    const float th = 6.28318530717958647692f * xv;
    float s1, c1;
    sincosf(th, &s1, &c1);
    float sh = s1, ch = c1;
    float acc = fmaf(cc[0], ch, sc[0] * sh);
    #pragma unroll 4
    for (int h = 1; h < NH_; h++) {
        const float cn = ch * c1 - sh * s1;
        const float sn = sh * c1 + ch * s1;
        ch = cn; sh = sn;
        acc = fmaf(cc[h], ch, acc);
        acc = fmaf(sc[h], sh, acc);
    }
    out[b * S_ + sI] = acc;
}

// ---------------- launcher ----------------
extern "C" void kernel_launch(void* const* d_in, const int* in_sizes, int n_in,
                              void* d_out, int out_size) {
    const float* target_x = (const float*)d_in[0];
    const float* z        = (const float*)d_in[1];
    /* d_in[2] = x, unused by the reference */
    const float* emb      = (const float*)d_in[3];
    const float* w_in     = (const float*)d_in[4];
    const float* b_in     = (const float*)d_in[5];
    const float* w_h      = (const float*)d_in[6];
    const float* b_h      = (const float*)d_in[7];
    const float* w_out    = (const float*)d_in[8];
    const float* b_out    = (const float*)d_in[9];
    float* out = (float*)d_out;

    cudaFuncSetAttribute(k_mma_gemm<0>, cudaFuncAttributeMaxDynamicSharedMemorySize, SMEM_DYN);
    cudaFuncSetAttribute(k_mma_gemm<1>, cudaFuncAttributeMaxDynamicSharedMemorySize, SMEM_DYN);
    cudaFuncSetAttribute(k_mma_gemm<2>, cudaFuncAttributeMaxDynamicSharedMemorySize, SMEM_DYN);

    k_wprep<<<dim3(16, 16, 3), dim3(32, 8)>>>(w_h);
    k_pre<<<dim3(HID_ / 256, B_ + NH_), 256>>>(z, emb, w_in, b_in, b_out);

    k_mma_gemm<1><<<dim3(HID_ / BN_, M_ / BM_), 256, SMEM_DYN>>>(0, 0, 0, b_h + 0 * HID_, w_out);
    k_mma_gemm<0><<<dim3(HID_ / BN_, M_ / BM_), 256, SMEM_DYN>>>(1, 0, 1, b_h + 1 * HID_, w_out);
    k_mma_gemm<2><<<dim3(HID_ / BN_, M_ / BM_), 256, SMEM_DYN>>>(2, 1, 0, b_h + 2 * HID_, w_out);

    k_synth<<<dim3(S_ / 256, B_), 256>>>(target_x, out);
}

// round 9
// speedup vs baseline: 2.2317x; 1.0883x over previous
#include <cuda_runtime.h>
#include <cuda_bf16.h>
#include <math.h>
#include <stdint.h>

#define B_    64
#define S_    4096
#define E_    266
#define HID_  512
#define NH_   128
#define M_    (B_ * NH_)   /* 8192 rows */
#define KC_   32           /* K chunk */
#define NCH_  (HID_ / KC_) /* 16 chunks */
#define SPAD_ 40           /* padded smem row stride in bf16 */
#define BM_   256          /* CTA tile M */
#define BN_   128          /* CTA tile N */

#define ROWB_     (SPAD_ * 2)
#define OFF_AH    0
#define OFF_AL    (BM_ * ROWB_)
#define OFF_BH    (2 * BM_ * ROWB_)
#define OFF_BL    (2 * BM_ * ROWB_ + BN_ * ROWB_)
#define STAGE_B   (2 * BM_ * ROWB_ + 2 * BN_ * ROWB_)
#define NSTAGE_   3
#define SMEM_DYN  (NSTAGE_ * STAGE_B)

__device__ __align__(16) __nv_bfloat16 g_ahi[2][M_ * HID_];
__device__ __align__(16) __nv_bfloat16 g_alo[2][M_ * HID_];
__device__ __align__(16) __nv_bfloat16 g_wthi[3][HID_ * HID_];
__device__ __align__(16) __nv_bfloat16 g_wtlo[3][HID_ * HID_];
__device__ float g_zw[B_ * HID_];
__device__ float g_ew[NH_ * HID_];
__device__ float g_sinc[M_];
__device__ float g_cosc[M_];

__device__ __forceinline__ float silu(float v) {
    return __fdividef(v, 1.0f + __expf(-v));
}
__device__ __forceinline__ uint32_t smem_u32(const void* p) {
    uint32_t a;
    asm("{ .reg .u64 t; cvta.to.shared.u64 t, %1; cvt.u32.u64 %0, t; }" : "=r"(a) : "l"(p));
    return a;
}
__device__ __forceinline__ void cp16(uint32_t sm, const void* g) {
    asm volatile("cp.async.cg.shared.global [%0], [%1], 16;" :: "r"(sm), "l"(g));
}
__device__ __forceinline__ void cp_commit() {
    asm volatile("cp.async.commit_group;" ::: "memory");
}
template <int N>
__device__ __forceinline__ void cp_wait() {
    asm volatile("cp.async.wait_group %0;" :: "n"(N) : "memory");
}
__device__ __forceinline__ void ldsm_x4(uint32_t* r, uint32_t addr) {
    asm volatile("ldmatrix.sync.aligned.m8n8.x4.shared.b16 {%0,%1,%2,%3}, [%4];"
                 : "=r"(r[0]), "=r"(r[1]), "=r"(r[2]), "=r"(r[3]) : "r"(addr));
}
__device__ __forceinline__ void mma_bf16(float* c, const uint32_t* a, const uint32_t* b) {
    asm volatile("mma.sync.aligned.m16n8k16.row.col.f32.bf16.bf16.f32 "
                 "{%0,%1,%2,%3}, {%4,%5,%6,%7}, {%8,%9}, {%0,%1,%2,%3};"
                 : "+f"(c[0]), "+f"(c[1]), "+f"(c[2]), "+f"(c[3])
                 : "r"(a[0]), "r"(a[1]), "r"(a[2]), "r"(a[3]), "r"(b[0]), "r"(b[1]));
}
__device__ __forceinline__ void split_store(char* sm_hi, char* sm_lo, int off,
                                            float v0, float v1, float v2, float v3) {
    const __nv_bfloat16 h0 = __float2bfloat16(v0), h1 = __float2bfloat16(v1);
    const __nv_bfloat16 h2 = __float2bfloat16(v2), h3 = __float2bfloat16(v3);
    const __nv_bfloat16 l0 = __float2bfloat16(v0 - __bfloat162float(h0));
    const __nv_bfloat16 l1 = __float2bfloat16(v1 - __bfloat162float(h1));
    const __nv_bfloat16 l2 = __float2bfloat16(v2 - __bfloat162float(h2));
    const __nv_bfloat16 l3 = __float2bfloat16(v3 - __bfloat162float(h3));
    ushort4 ph, pl;
    ph.x = __bfloat16_as_ushort(h0); ph.y = __bfloat16_as_ushort(h1);
    ph.z = __bfloat16_as_ushort(h2); ph.w = __bfloat16_as_ushort(h3);
    pl.x = __bfloat16_as_ushort(l0); pl.y = __bfloat16_as_ushort(l1);
    pl.z = __bfloat16_as_ushort(l2); pl.w = __bfloat16_as_ushort(l3);
    *(ushort4*)(sm_hi + off) = ph;
    *(ushort4*)(sm_lo + off) = pl;
}

// ---------------- fused prep: weight transpose/split + zw/ew + coeff init ----
__global__ void k_prep(const float* __restrict__ w_h,
                       const float* __restrict__ z, const float* __restrict__ emb,
                       const float* __restrict__ w_in, const float* __restrict__ b_in,
                       const float* __restrict__ b_out) {
    if (blockIdx.x < 768) {
        __shared__ float t[32][33];
        const int idx = blockIdx.x;
        const int l = idx >> 8;
        const int rem = idx & 255;
        const int k0 = (rem >> 4) * 32, n0 = (rem & 15) * 32;
        const int tx = threadIdx.x & 31, ty = threadIdx.x >> 5;
        const float* W = w_h + (size_t)l * HID_ * HID_;
        for (int i = ty; i < 32; i += 8)
            t[i][tx] = W[(size_t)(k0 + i) * HID_ + n0 + tx];
        __syncthreads();
        for (int i = ty; i < 32; i += 8) {
            const float v = t[tx][i];
            const __nv_bfloat16 hi = __float2bfloat16(v);
            const __nv_bfloat16 lo = __float2bfloat16(v - __bfloat162float(hi));
            g_wthi[l][(size_t)(n0 + i) * HID_ + k0 + tx] = hi;
            g_wtlo[l][(size_t)(n0 + i) * HID_ + k0 + tx] = lo;
        }
    } else {
        __shared__ float vr[E_];
        const int idx2 = blockIdx.x - 768;
        const int dblk = idx2 & 1;
        const int y = idx2 >> 1;
        const bool is_z = (y < B_);
        const int row = is_z ? y : y - B_;
        const float* src = (is_z ? z : emb) + (size_t)row * E_;
        for (int e = threadIdx.x; e < E_; e += blockDim.x) vr[e] = src[e];
        __syncthreads();
        const int d = dblk * 256 + threadIdx.x;
        float acc = is_z ? 0.f : b_in[d];
        #pragma unroll 2
        for (int e = 0; e < E_; e++) acc = fmaf(vr[e], __ldg(w_in + e * HID_ + d), acc);
        if (is_z) g_zw[row * HID_ + d] = acc;
        else      g_ew[row * HID_ + d] = acc;
        if (!is_z && row < 16) {
            const int i = row * HID_ + d;
            g_sinc[i] = b_out[0];
            g_cosc[i] = b_out[1];
        }
    }
}

// ---------------- fused MLP GEMM (CTA 256x128, warp 64x64, 3-stage pipe) ----
template <int MODE>
__global__ void __launch_bounds__(256, 1) k_mma_gemm(int layer, int src, int dst,
                                                     const float* __restrict__ bias,
                                                     const float* __restrict__ w_out) {
    extern __shared__ char smem[];
    const int tid = threadIdx.x;
    const int wid = tid >> 5;
    const int lane = tid & 31;
    const int wm = wid & 3;
    const int wn = wid >> 2;
    const int m0 = blockIdx.y * BM_;
    const int n0 = blockIdx.x * BN_;

    const __nv_bfloat16* __restrict__ Ahi  = g_ahi[src];
    const __nv_bfloat16* __restrict__ Alo  = g_alo[src];
    const __nv_bfloat16* __restrict__ Wthi = g_wthi[layer];
    const __nv_bfloat16* __restrict__ Wtlo = g_wtlo[layer];
    __nv_bfloat16* __restrict__ Dhi = g_ahi[dst];
    __nv_bfloat16* __restrict__ Dlo = g_alo[dst];

    const uint32_t smb = smem_u32(smem);

    auto stage_load = [&](int c) {
        const int k0 = c * KC_;
        const int buf = c % NSTAGE_;
        char* sb = smem + buf * STAGE_B;
        const uint32_t sbu = smb + buf * STAGE_B;
        if (MODE != 1) {
            #pragma unroll
            for (int i = 0; i < 8; i++) {
                const int idx = tid + i * 256;
                const int t = idx >> 10;
                const int j = idx & 1023;
                const int r = j >> 2;
                const int c16 = j & 3;
                const uint32_t sm = sbu + (t ? OFF_AL : OFF_AH) + r * ROWB_ + c16 * 16;
                const __nv_bfloat16* gp = (t ? Alo : Ahi) + (size_t)(m0 + r) * HID_ + k0 + c16 * 8;
                cp16(sm, gp);
            }
        } else {
            #pragma unroll
            for (int i = 0; i < 8; i++) {
                const int idx = tid + i * 256;
                const int r = idx >> 3;
                const int q = idx & 7;
                const int row = m0 + r;
                const int bb = row >> 7;
                const int hh = row & (NH_ - 1);
                const float4 zv = *(const float4*)(g_zw + bb * HID_ + k0 + q * 4);
                const float4 ev = *(const float4*)(g_ew + hh * HID_ + k0 + q * 4);
                split_store(sb + OFF_AH, sb + OFF_AL, r * ROWB_ + q * 8,
                            silu(zv.x + ev.x), silu(zv.y + ev.y),
                            silu(zv.z + ev.z), silu(zv.w + ev.w));
            }
        }
        #pragma unroll
        for (int i = 0; i < 4; i++) {
            const int idx = tid + i * 256;
            const int t = idx >> 9;
            const int j = idx & 511;
            const int r = j >> 2;
            const int c16 = j & 3;
            const uint32_t sm = sbu + (t ? OFF_BL : OFF_BH) + r * ROWB_ + c16 * 16;
            const __nv_bfloat16* gp = (t ? Wtlo : Wthi) + (size_t)(n0 + r) * HID_ + k0 + c16 * 8;
            cp16(sm, gp);
        }
        cp_commit();
    };

    float acc[4][8][4];
    #pragma unroll
    for (int i = 0; i < 4; i++)
        #pragma unroll
        for (int j = 0; j < 8; j++)
            #pragma unroll
            for (int q = 0; q < 4; q++) acc[i][j][q] = 0.f;

    const int arow = wm * 64 + (lane & 15);
    const int acol = (lane >> 4) << 3;
    const int brow = wn * 64 + ((lane >> 4) & 1) * 8 + (lane & 7);
    const int bcol = ((lane >> 3) & 1) * 8;

    stage_load(0);

    for (int c = 0; c < NCH_; c++) {
        if (c + 1 < NCH_) {
            stage_load(c + 1);
            cp_wait<1>();
        } else {
            cp_wait<0>();
        }
        __syncthreads();

        const uint32_t sbu = smb + (c % NSTAGE_) * STAGE_B;
        const uint32_t aH = sbu + OFF_AH, aL = sbu + OFF_AL;
        const uint32_t bH = sbu + OFF_BH, bL = sbu + OFF_BL;

        #pragma unroll
        for (int ks = 0; ks < 2; ks++) {
            const int kc = ks * 16;
            uint32_t bh[16], bl[16];
            #pragma unroll
            for (int np = 0; np < 4; np++) {
                const uint32_t bo = (uint32_t)((brow + np * 16) * SPAD_ + bcol + kc) * 2;
                ldsm_x4(bh + np * 4, bH + bo);
                ldsm_x4(bl + np * 4, bL + bo);
            }
            #pragma unroll
            for (int mt = 0; mt < 4; mt++) {
                const uint32_t ao = (uint32_t)((arow + mt * 16) * SPAD_ + acol + kc) * 2;
                uint32_t ah[4], al[4];
                ldsm_x4(ah, aH + ao);
                ldsm_x4(al, aL + ao);
                #pragma unroll
                for (int nt = 0; nt < 8; nt++) {
                    mma_bf16(acc[mt][nt], ah, bh + nt * 2);
                    mma_bf16(acc[mt][nt], ah, bl + nt * 2);
                    mma_bf16(acc[mt][nt], al, bh + nt * 2);
                }
            }
        }
    }

    const int g = lane >> 2;
    const int cpair = (lane & 3) * 2;

    if (MODE != 2) {
        #pragma unroll
        for (int mt = 0; mt < 4; mt++) {
            #pragma unroll
            for (int nt = 0; nt < 8; nt++) {
                const int row = m0 + wm * 64 + mt * 16 + g;
                const int col = n0 + wn * 64 + nt * 8 + cpair;
                const float b0 = __ldg(bias + col);
                const float b1 = __ldg(bias + col + 1);
                #pragma unroll
                for (int half = 0; half < 2; half++) {
                    const int r = row + half * 8;
                    const float v0 = silu(acc[mt][nt][half * 2 + 0] + b0);
                    const float v1 = silu(acc[mt][nt][half * 2 + 1] + b1);
                    const __nv_bfloat16 h0 = __float2bfloat16(v0);
                    const __nv_bfloat16 h1 = __float2bfloat16(v1);
                    const __nv_bfloat16 l0 = __float2bfloat16(v0 - __bfloat162float(h0));
                    const __nv_bfloat16 l1 = __float2bfloat16(v1 - __bfloat162float(h1));
                    __nv_bfloat162 ph, pl;
                    ph.x = h0; ph.y = h1;
                    pl.x = l0; pl.y = l1;
                    *(__nv_bfloat162*)(Dhi + (size_t)r * HID_ + col) = ph;
                    *(__nv_bfloat162*)(Dlo + (size_t)r * HID_ + col) = pl;
                }
            }
        }
    } else {
        #pragma unroll
        for (int mt = 0; mt < 4; mt++) {
            #pragma unroll
            for (int half = 0; half < 2; half++) {
                float s = 0.f, cs = 0.f;
                #pragma unroll
                for (int nt = 0; nt < 8; nt++) {
                    const int col = n0 + wn * 64 + nt * 8 + cpair;
                    const float b0 = __ldg(bias + col);
                    const float b1 = __ldg(bias + col + 1);
                    const float v0 = silu(acc[mt][nt][half * 2 + 0] + b0);
                    const float v1 = silu(acc[mt][nt][half * 2 + 1] + b1);
                    s  = fmaf(v0, __ldg(w_out + 2 * col + 0), s);
                    cs = fmaf(v0, __ldg(w_out + 2 * col + 1), cs);
                    s  = fmaf(v1, __ldg(w_out + 2 * col + 2), s);
                    cs = fmaf(v1, __ldg(w_out + 2 * col + 3), cs);
                }
                s  += __shfl_xor_sync(0xffffffffu, s, 1);
                s  += __shfl_xor_sync(0xffffffffu, s, 2);
                cs += __shfl_xor_sync(0xffffffffu, cs, 1);
                cs += __shfl_xor_sync(0xffffffffu, cs, 2);
                if ((lane & 3) == 0) {
                    const int row = m0 + wm * 64 + mt * 16 + g + half * 8;
                    atomicAdd(&g_sinc[row], s);
                    atomicAdd(&g_cosc[row], cs);
                }
            }
        }
    }
}

// ---------------- synthesis: 2-chain integer-frequency recurrence ----------------
__global__ void k_synth(const float* __restrict__ tx, float* __restrict__ out) {
    __shared__ float sc[NH_], cc[NH_];
    const int b = blockIdx.y;
    if (threadIdx.x < NH_) {
        sc[threadIdx.x] = g_sinc[b * NH_ + threadIdx.x];
        cc[threadIdx.x] = g_cosc[b * NH_ + threadIdx.x];
    }
    __syncthreads();
    const int sI = blockIdx.x * blockDim.x + threadIdx.x;
    const float xv = tx[b * S_ + sI];
    const float th = 6.28318530717958647692f * xv;
    float s1, c1;
    sincosf(th, &s1, &c1);
    const float c2 = c1 * c1 - s1 * s1;
    const float s2 = 2.f * s1 * c1;
    float ca = c1, sa = s1;
    float cb = c2, sb = s2;
    float acc0 = fmaf(cc[0], ca, sc[0] * sa);
    float acc1 = fmaf(cc[1], cb, sc[1] * sb);
    #pragma unroll 4
    for (int i = 1; i < 64; i++) {
        const float can = ca * c2 - sa * s2;
        const float san = sa * c2 + ca * s2;
        ca = can; sa = san;
        const float cbn = cb * c2 - sb * s2;
        const float sbn = sb * c2 + cb * s2;
        cb = cbn; sb = sbn;
        acc0 = fmaf(cc[2 * i], ca, acc0);
        acc0 = fmaf(sc[2 * i], sa, acc0);
        acc1 = fmaf(cc[2 * i + 1], cb, acc1);
        acc1 = fmaf(sc[2 * i + 1], sb, acc1);
    }
    out[b * S_ + sI] = acc0 + acc1;
}

// ---------------- launcher ----------------
extern "C" void kernel_launch(void* const* d_in, const int* in_sizes, int n_in,
                              void* d_out, int out_size) {
    const float* target_x = (const float*)d_in[0];
    const float* z        = (const float*)d_in[1];
    /* d_in[2] = x, unused by the reference */
    const float* emb      = (const float*)d_in[3];
    const float* w_in     = (const float*)d_in[4];
    const float* b_in     = (const float*)d_in[5];
    const float* w_h      = (const float*)d_in[6];
    const float* b_h      = (const float*)d_in[7];
    const float* w_out    = (const float*)d_in[8];
    const float* b_out    = (const float*)d_in[9];
    float* out = (float*)d_out;

    cudaFuncSetAttribute(k_mma_gemm<0>, cudaFuncAttributeMaxDynamicSharedMemorySize, SMEM_DYN);
    cudaFuncSetAttribute(k_mma_gemm<1>, cudaFuncAttributeMaxDynamicSharedMemorySize, SMEM_DYN);
    cudaFuncSetAttribute(k_mma_gemm<2>, cudaFuncAttributeMaxDynamicSharedMemorySize, SMEM_DYN);

    k_prep<<<1152, 256>>>(w_h, z, emb, w_in, b_in, b_out);

    k_mma_gemm<1><<<dim3(HID_ / BN_, M_ / BM_), 256, SMEM_DYN>>>(0, 0, 0, b_h + 0 * HID_, w_out);
    k_mma_gemm<0><<<dim3(HID_ / BN_, M_ / BM_), 256, SMEM_DYN>>>(1, 0, 1, b_h + 1 * HID_, w_out);
    k_mma_gemm<2><<<dim3(HID_ / BN_, M_ / BM_), 256, SMEM_DYN>>>(2, 1, 0, b_h + 2 * HID_, w_out);

    k_synth<<<dim3(S_ / 256, B_), 256>>>(target_x, out);
}